// round 2
// baseline (speedup 1.0000x reference)
#include <cuda_runtime.h>

// ---------------------------------------------------------------------------
// OpticFlowMask: motion mask + flow inversion (last-write-wins scatter)
// B=12, H=192, W=640.
// Output layout (float32): [motion_mask (B*H*W)][bwd_flow (B*2*H*W)][seg_ref (B*H*W)]
// Segmentation input is int32 (bool promoted by harness).
// ---------------------------------------------------------------------------

#define BB   12
#define HH   192
#define WW   640
#define HWSZ (HH * WW)                 // 122880
#define NPIX (BB * HWSZ)               // 1474560
#define TPB  256
#define NBLK (NPIX / TPB)              // 5760 (exact)
#define BPB  (HWSZ / TPB)              // 480 blocks per batch (exact)
#define EPSF 1e-7f
#define THR  0.98f

// reduction slots: 0=fmin 1=fmax 2=smin 3=smax 4=cmin 5=cmax (monotonic-encoded)
__device__ unsigned g_red[6];
__device__ int g_winner[NPIX];

__device__ __forceinline__ unsigned fenc(float f) {
    unsigned u = __float_as_uint(f);
    return (u & 0x80000000u) ? ~u : (u | 0x80000000u);
}
__device__ __forceinline__ float fdec(unsigned u) {
    unsigned b = (u & 0x80000000u) ? (u & 0x7fffffffu) : ~u;
    return __uint_as_float(b);
}

template <int SMIN, int SMAX>
__device__ __forceinline__ void block_minmax(float vmin, float vmax) {
#pragma unroll
    for (int o = 16; o; o >>= 1) {
        vmin = fminf(vmin, __shfl_xor_sync(0xffffffffu, vmin, o));
        vmax = fmaxf(vmax, __shfl_xor_sync(0xffffffffu, vmax, o));
    }
    __shared__ float sm1[TPB / 32], sm2[TPB / 32];
    int w = threadIdx.x >> 5, l = threadIdx.x & 31;
    if (l == 0) { sm1[w] = vmin; sm2[w] = vmax; }
    __syncthreads();
    if (w == 0) {
        vmin = (l < TPB / 32) ? sm1[l] : __int_as_float(0x7f800000);   // +inf
        vmax = (l < TPB / 32) ? sm2[l] : __int_as_float(0xff800000);   // -inf
#pragma unroll
        for (int o = 4; o; o >>= 1) {
            vmin = fminf(vmin, __shfl_xor_sync(0xffffffffu, vmin, o));
            vmax = fmaxf(vmax, __shfl_xor_sync(0xffffffffu, vmax, o));
        }
        if (l == 0) {
            atomicMin(&g_red[SMIN], fenc(vmin));
            atomicMax(&g_red[SMAX], fenc(vmax));
        }
    }
}

// Per-block setup of P = (K @ pose)[:3,:] (12 floats) and invK[:3,:3] (9 floats)
__device__ __forceinline__ void setup_mats(const float* Kmat, const float* invK,
                                           const float* pose, int b,
                                           float* sP, float* siK) {
    int t = threadIdx.x;
    if (t < 12) {
        int i = t >> 2, j = t & 3;
        const float* Kb = Kmat + b * 16;
        const float* Pb = pose + b * 16;
        sP[t] = Kb[i * 4 + 0] * Pb[0 * 4 + j] + Kb[i * 4 + 1] * Pb[1 * 4 + j] +
                Kb[i * 4 + 2] * Pb[2 * 4 + j] + Kb[i * 4 + 3] * Pb[3 * 4 + j];
    } else if (t < 21) {
        int r = (t - 12) / 3, c = (t - 12) % 3;
        siK[t - 12] = invK[b * 16 + r * 4 + c];
    }
    __syncthreads();
}

__device__ __forceinline__ void static_flow(const float* sP, const float* siK,
                                            float x, float y, float d,
                                            float& sx, float& sy) {
    float dx = siK[0] * x + siK[1] * y + siK[2];
    float dy = siK[3] * x + siK[4] * y + siK[5];
    float dz = siK[6] * x + siK[7] * y + siK[8];
    float cx = d * dx, cy = d * dy, cz = d * dz;
    float c0 = sP[0] * cx + sP[1] * cy + sP[2]  * cz + sP[3];
    float c1 = sP[4] * cx + sP[5] * cy + sP[6]  * cz + sP[7];
    float c2 = sP[8] * cx + sP[9] * cy + sP[10] * cz + sP[11];
    float den = c2 + EPSF;
    sx = c0 / den - x;
    sy = c1 / den - y;
}

__global__ void k_reset() {
    int t = threadIdx.x;
    if (t < 6) g_red[t] = (t & 1) ? 0u : 0xffffffffu;
}

// Pass 1: flow min/max + static min/max; reset winner array.
__global__ void __launch_bounds__(TPB) k_reduce1(
        const float* __restrict__ flow, const float* __restrict__ depth,
        const float* __restrict__ Kmat, const float* __restrict__ invK,
        const float* __restrict__ pose) {
    __shared__ float sP[12], siK[9];
    int b = blockIdx.x / BPB;
    setup_mats(Kmat, invK, pose, b, sP, siK);

    int idx = blockIdx.x * TPB + threadIdx.x;
    g_winner[idx] = -1;
    int p = idx - b * HWSZ;
    int y = p / WW, x = p - y * WW;
    float fx = flow[b * 2 * HWSZ + p];
    float fy = flow[b * 2 * HWSZ + HWSZ + p];
    float d  = depth[idx];
    float sx, sy;
    static_flow(sP, siK, (float)x, (float)y, d, sx, sy);

    block_minmax<0, 1>(fminf(fx, fy), fmaxf(fx, fy));
    block_minmax<2, 3>(fminf(sx, sy), fmaxf(sx, sy));
}

// Pass 2: check = |flow_n - static_n|, reduce min/max.
__global__ void __launch_bounds__(TPB) k_reduce2(
        const float* __restrict__ flow, const float* __restrict__ depth,
        const float* __restrict__ Kmat, const float* __restrict__ invK,
        const float* __restrict__ pose) {
    __shared__ float sP[12], siK[9];
    int b = blockIdx.x / BPB;
    setup_mats(Kmat, invK, pose, b, sP, siK);

    float fmn = fdec(g_red[0]), fmx = fdec(g_red[1]);
    float smn = fdec(g_red[2]), smx = fdec(g_red[3]);

    int idx = blockIdx.x * TPB + threadIdx.x;
    int p = idx - b * HWSZ;
    int y = p / WW, x = p - y * WW;
    float fx = flow[b * 2 * HWSZ + p];
    float fy = flow[b * 2 * HWSZ + HWSZ + p];
    float d  = depth[idx];
    float sx, sy;
    static_flow(sP, siK, (float)x, (float)y, d, sx, sy);

    float fnx = 2.0f * (fx - fmn) / (fmx - fmn) - 1.0f;
    float fny = 2.0f * (fy - fmn) / (fmx - fmn) - 1.0f;
    float snx = 2.0f * (sx - smn) / (smx - smn) - 1.0f;
    float sny = 2.0f * (sy - smn) / (smx - smn) - 1.0f;
    float ddx = fnx - snx, ddy = fny - sny;
    float c = sqrtf(ddx * ddx + ddy * ddy);

    block_minmax<4, 5>(c, c);
}

// Pass 3: motion mask + zero scatter regions + winner election (atomicMax).
__global__ void __launch_bounds__(TPB) k_main(
        const float* __restrict__ flow, const float* __restrict__ depth,
        const float* __restrict__ Kmat, const float* __restrict__ invK,
        const float* __restrict__ pose, float* __restrict__ out) {
    __shared__ float sP[12], siK[9];
    int b = blockIdx.x / BPB;
    setup_mats(Kmat, invK, pose, b, sP, siK);

    float fmn = fdec(g_red[0]), fmx = fdec(g_red[1]);
    float smn = fdec(g_red[2]), smx = fdec(g_red[3]);
    float cmn = fdec(g_red[4]), cmx = fdec(g_red[5]);

    int idx = blockIdx.x * TPB + threadIdx.x;
    int p = idx - b * HWSZ;
    int y = p / WW, x = p - y * WW;
    float fx = flow[b * 2 * HWSZ + p];
    float fy = flow[b * 2 * HWSZ + HWSZ + p];
    float d  = depth[idx];
    float sx, sy;
    static_flow(sP, siK, (float)x, (float)y, d, sx, sy);

    float fnx = 2.0f * (fx - fmn) / (fmx - fmn) - 1.0f;
    float fny = 2.0f * (fy - fmn) / (fmx - fmn) - 1.0f;
    float snx = 2.0f * (sx - smn) / (smx - smn) - 1.0f;
    float sny = 2.0f * (sy - smn) / (smx - smn) - 1.0f;
    float ddx = fnx - snx, ddy = fny - sny;
    float c = sqrtf(ddx * ddx + ddy * ddy);
    float cn = (c - cmn) / (cmx - cmn);

    out[idx] = (cn < THR) ? 1.0f : 0.0f;
    // zero bwd_flow + seg_ref regions (scatter targets)
    out[NPIX + b * 2 * HWSZ + p]        = 0.0f;
    out[NPIX + b * 2 * HWSZ + HWSZ + p] = 0.0f;
    out[3 * NPIX + idx]                 = 0.0f;

    // winner election: jnp.round = ties-to-even -> rintf; clip after int cast
    float rcx = rintf((float)x + fx);
    float rcy = rintf((float)y + fy);
    int cxi = min(max((int)rcx, 0), WW - 1);
    int cyi = min(max((int)rcy, 0), HH - 1);
    atomicMax(&g_winner[b * HWSZ + cyi * WW + cxi], p);
}

// Pass 4: winner-gated scatter of -flow and segmentation (int32 input).
__global__ void __launch_bounds__(TPB) k_scatter(
        const float* __restrict__ flow, const int* __restrict__ seg,
        float* __restrict__ out) {
    int idx = blockIdx.x * TPB + threadIdx.x;
    int b = blockIdx.x / BPB;
    int p = idx - b * HWSZ;
    int y = p / WW, x = p - y * WW;
    float fx = flow[b * 2 * HWSZ + p];
    float fy = flow[b * 2 * HWSZ + HWSZ + p];
    float rcx = rintf((float)x + fx);
    float rcy = rintf((float)y + fy);
    int cxi = min(max((int)rcx, 0), WW - 1);
    int cyi = min(max((int)rcy, 0), HH - 1);
    int tgt = cyi * WW + cxi;
    if (g_winner[b * HWSZ + tgt] == p) {
        out[NPIX + b * 2 * HWSZ + tgt]        = -fx;
        out[NPIX + b * 2 * HWSZ + HWSZ + tgt] = -fy;
        out[3 * NPIX + b * HWSZ + tgt]        = seg[b * HWSZ + p] ? 1.0f : 0.0f;
    }
}

extern "C" void kernel_launch(void* const* d_in, const int* in_sizes, int n_in,
                              void* d_out, int out_size) {
    const float* flow  = (const float*)d_in[0];
    const float* depth = (const float*)d_in[1];
    const float* Kmat  = (const float*)d_in[2];
    const float* invK  = (const float*)d_in[3];
    const float* pose  = (const float*)d_in[4];
    const int*   seg   = (const int*)d_in[5];
    float* out = (float*)d_out;

    k_reset<<<1, 32>>>();
    k_reduce1<<<NBLK, TPB>>>(flow, depth, Kmat, invK, pose);
    k_reduce2<<<NBLK, TPB>>>(flow, depth, Kmat, invK, pose);
    k_main<<<NBLK, TPB>>>(flow, depth, Kmat, invK, pose, out);
    k_scatter<<<NBLK, TPB>>>(flow, seg, out);
}

// round 3
// speedup vs baseline: 1.6799x; 1.6799x over previous
#include <cuda_runtime.h>

// ---------------------------------------------------------------------------
// OpticFlowMask: motion mask + flow inversion (last-write-wins via winner
// election + GATHER). B=12, H=192, W=640.
// Output layout (float32): [motion_mask (N)][bwd_flow (2N)][seg_ref (N)]
// Segmentation input is int32.
// ---------------------------------------------------------------------------

#define BB    12
#define HH    192
#define WW    640
#define HWSZ  (HH * WW)                 // 122880
#define NPIX  (BB * HWSZ)               // 1474560
#define TPB   256
#define VEC   4
#define PXT   (TPB * VEC)               // 1024 px per block
#define BPB2  (HWSZ / PXT)              // 120 blocks per batch (exact)
#define NBLK2 (BB * BPB2)               // 1440 blocks
#define EPSF  1e-7f
#define THR   0.98f

// reduction slots: 0=fmin 1=fmax 2=smin 3=smax 4=cmin 5=cmax (monotonic-encoded)
__device__ unsigned g_red[6];
__device__ int g_winner[NPIX];

__device__ __forceinline__ unsigned fenc(float f) {
    unsigned u = __float_as_uint(f);
    return (u & 0x80000000u) ? ~u : (u | 0x80000000u);
}
__device__ __forceinline__ float fdec(unsigned u) {
    unsigned b = (u & 0x80000000u) ? (u & 0x7fffffffu) : ~u;
    return __uint_as_float(b);
}

template <int SMIN, int SMAX>
__device__ __forceinline__ void block_minmax(float vmin, float vmax) {
#pragma unroll
    for (int o = 16; o; o >>= 1) {
        vmin = fminf(vmin, __shfl_xor_sync(0xffffffffu, vmin, o));
        vmax = fmaxf(vmax, __shfl_xor_sync(0xffffffffu, vmax, o));
    }
    __shared__ float sm1[TPB / 32], sm2[TPB / 32];
    int w = threadIdx.x >> 5, l = threadIdx.x & 31;
    if (l == 0) { sm1[w] = vmin; sm2[w] = vmax; }
    __syncthreads();
    if (w == 0) {
        vmin = (l < TPB / 32) ? sm1[l] : __int_as_float(0x7f800000);   // +inf
        vmax = (l < TPB / 32) ? sm2[l] : __int_as_float(0xff800000);   // -inf
#pragma unroll
        for (int o = 4; o; o >>= 1) {
            vmin = fminf(vmin, __shfl_xor_sync(0xffffffffu, vmin, o));
            vmax = fmaxf(vmax, __shfl_xor_sync(0xffffffffu, vmax, o));
        }
        if (l == 0) {
            atomicMin(&g_red[SMIN], fenc(vmin));
            atomicMax(&g_red[SMAX], fenc(vmax));
        }
    }
}

// Per-block setup of P = (K @ pose)[:3,:] (12 floats) and invK[:3,:3] (9 floats)
__device__ __forceinline__ void setup_mats(const float* Kmat, const float* invK,
                                           const float* pose, int b,
                                           float* sP, float* siK) {
    int t = threadIdx.x;
    if (t < 12) {
        int i = t >> 2, j = t & 3;
        const float* Kb = Kmat + b * 16;
        const float* Pb = pose + b * 16;
        sP[t] = Kb[i * 4 + 0] * Pb[0 * 4 + j] + Kb[i * 4 + 1] * Pb[1 * 4 + j] +
                Kb[i * 4 + 2] * Pb[2 * 4 + j] + Kb[i * 4 + 3] * Pb[3 * 4 + j];
    } else if (t < 21) {
        int r = (t - 12) / 3, c = (t - 12) % 3;
        siK[t - 12] = invK[b * 16 + r * 4 + c];
    }
    __syncthreads();
}

// static flow for 4 consecutive x positions at fixed y
__device__ __forceinline__ void static_flow4(const float* sP, const float* siK,
                                             float x0, float y, const float4& d4,
                                             float* sx, float* sy) {
    const float dv[4] = {d4.x, d4.y, d4.z, d4.w};
#pragma unroll
    for (int i = 0; i < 4; i++) {
        float x = x0 + (float)i;
        float dx = siK[0] * x + (siK[1] * y + siK[2]);
        float dy = siK[3] * x + (siK[4] * y + siK[5]);
        float dz = siK[6] * x + (siK[7] * y + siK[8]);
        float d = dv[i];
        float cx = d * dx, cy = d * dy, cz = d * dz;
        float c0 = sP[0] * cx + sP[1] * cy + sP[2]  * cz + sP[3];
        float c1 = sP[4] * cx + sP[5] * cy + sP[6]  * cz + sP[7];
        float c2 = sP[8] * cx + sP[9] * cy + sP[10] * cz + sP[11];
        float den = c2 + EPSF;
        sx[i] = c0 / den - x;
        sy[i] = c1 / den - y;
    }
}

__global__ void k_reset() {
    int t = threadIdx.x;
    if (t < 6) g_red[t] = (t & 1) ? 0u : 0xffffffffu;
}

// Pass 1: flow min/max + static min/max; reset winner array.
__global__ void __launch_bounds__(TPB) k_reduce1(
        const float* __restrict__ flow, const float* __restrict__ depth,
        const float* __restrict__ Kmat, const float* __restrict__ invK,
        const float* __restrict__ pose) {
    __shared__ float sP[12], siK[9];
    int b = blockIdx.x / BPB2;
    setup_mats(Kmat, invK, pose, b, sP, siK);

    int p0 = (blockIdx.x - b * BPB2) * PXT + threadIdx.x * VEC;
    int y = p0 / WW, x0 = p0 - y * WW;
    const float4 fx4 = *(const float4*)(flow + b * 2 * HWSZ + p0);
    const float4 fy4 = *(const float4*)(flow + b * 2 * HWSZ + HWSZ + p0);
    const float4 d4  = *(const float4*)(depth + b * HWSZ + p0);
    *(int4*)(g_winner + b * HWSZ + p0) = make_int4(-1, -1, -1, -1);

    float sx[4], sy[4];
    static_flow4(sP, siK, (float)x0, (float)y, d4, sx, sy);

    float fmn = fminf(fminf(fminf(fx4.x, fx4.y), fminf(fx4.z, fx4.w)),
                      fminf(fminf(fy4.x, fy4.y), fminf(fy4.z, fy4.w)));
    float fmx = fmaxf(fmaxf(fmaxf(fx4.x, fx4.y), fmaxf(fx4.z, fx4.w)),
                      fmaxf(fmaxf(fy4.x, fy4.y), fmaxf(fy4.z, fy4.w)));
    float smn = fminf(fminf(fminf(sx[0], sx[1]), fminf(sx[2], sx[3])),
                      fminf(fminf(sy[0], sy[1]), fminf(sy[2], sy[3])));
    float smx = fmaxf(fmaxf(fmaxf(sx[0], sx[1]), fmaxf(sx[2], sx[3])),
                      fmaxf(fmaxf(sy[0], sy[1]), fmaxf(sy[2], sy[3])));

    block_minmax<0, 1>(fmn, fmx);
    block_minmax<2, 3>(smn, smx);
}

// Pass 2: check min/max + winner election (atomicMax; election is
// reduction-independent but must follow the winner reset in pass 1).
__global__ void __launch_bounds__(TPB) k_reduce2(
        const float* __restrict__ flow, const float* __restrict__ depth,
        const float* __restrict__ Kmat, const float* __restrict__ invK,
        const float* __restrict__ pose) {
    __shared__ float sP[12], siK[9];
    int b = blockIdx.x / BPB2;
    setup_mats(Kmat, invK, pose, b, sP, siK);

    float fmn = fdec(g_red[0]), fmx = fdec(g_red[1]);
    float smn = fdec(g_red[2]), smx = fdec(g_red[3]);
    float finv = 2.0f / (fmx - fmn), sinv = 2.0f / (smx - smn);

    int p0 = (blockIdx.x - b * BPB2) * PXT + threadIdx.x * VEC;
    int y = p0 / WW, x0 = p0 - y * WW;
    const float4 fx4 = *(const float4*)(flow + b * 2 * HWSZ + p0);
    const float4 fy4 = *(const float4*)(flow + b * 2 * HWSZ + HWSZ + p0);
    const float4 d4  = *(const float4*)(depth + b * HWSZ + p0);

    float sx[4], sy[4];
    static_flow4(sP, siK, (float)x0, (float)y, d4, sx, sy);

    const float fxv[4] = {fx4.x, fx4.y, fx4.z, fx4.w};
    const float fyv[4] = {fy4.x, fy4.y, fy4.z, fy4.w};
    float cmn = __int_as_float(0x7f800000), cmx = __int_as_float(0xff800000);
#pragma unroll
    for (int i = 0; i < 4; i++) {
        float ddx = (fxv[i] - fmn) * finv - (sx[i] - smn) * sinv;
        float ddy = (fyv[i] - fmn) * finv - (sy[i] - smn) * sinv;
        float c = sqrtf(ddx * ddx + ddy * ddy);
        cmn = fminf(cmn, c);
        cmx = fmaxf(cmx, c);
        // winner election: jnp.round = ties-to-even; clip after int cast
        int px = x0 + i;
        int cxi = min(max((int)rintf((float)px + fxv[i]), 0), WW - 1);
        int cyi = min(max((int)rintf((float)y + fyv[i]), 0), HH - 1);
        atomicMax(&g_winner[b * HWSZ + cyi * WW + cxi], p0 + i);
    }

    block_minmax<4, 5>(cmn, cmx);
}

// Pass 3: motion mask + gather of bwd_flow / seg_ref from winner indices.
__global__ void __launch_bounds__(TPB) k_main(
        const float* __restrict__ flow, const float* __restrict__ depth,
        const float* __restrict__ Kmat, const float* __restrict__ invK,
        const float* __restrict__ pose, const int* __restrict__ seg,
        float* __restrict__ out) {
    __shared__ float sP[12], siK[9];
    int b = blockIdx.x / BPB2;
    setup_mats(Kmat, invK, pose, b, sP, siK);

    float fmn = fdec(g_red[0]), fmx = fdec(g_red[1]);
    float smn = fdec(g_red[2]), smx = fdec(g_red[3]);
    float cmn = fdec(g_red[4]), cmx = fdec(g_red[5]);
    float finv = 2.0f / (fmx - fmn), sinv = 2.0f / (smx - smn);
    float cinv = 1.0f / (cmx - cmn);

    int p0 = (blockIdx.x - b * BPB2) * PXT + threadIdx.x * VEC;
    int y = p0 / WW, x0 = p0 - y * WW;
    const float* fb = flow + b * 2 * HWSZ;
    const float4 fx4 = *(const float4*)(fb + p0);
    const float4 fy4 = *(const float4*)(fb + HWSZ + p0);
    const float4 d4  = *(const float4*)(depth + b * HWSZ + p0);

    float sx[4], sy[4];
    static_flow4(sP, siK, (float)x0, (float)y, d4, sx, sy);

    const float fxv[4] = {fx4.x, fx4.y, fx4.z, fx4.w};
    const float fyv[4] = {fy4.x, fy4.y, fy4.z, fy4.w};
    float4 mask;
    float* mv = (float*)&mask;
#pragma unroll
    for (int i = 0; i < 4; i++) {
        float ddx = (fxv[i] - fmn) * finv - (sx[i] - smn) * sinv;
        float ddy = (fyv[i] - fmn) * finv - (sy[i] - smn) * sinv;
        float c = sqrtf(ddx * ddx + ddy * ddy);
        mv[i] = ((c - cmn) * cinv < THR) ? 1.0f : 0.0f;
    }
    *(float4*)(out + b * HWSZ + p0) = mask;

    // gather: winner source index per target pixel
    const int4 w4 = *(const int4*)(g_winner + b * HWSZ + p0);
    const int wv[4] = {w4.x, w4.y, w4.z, w4.w};
    const int* sb = seg + b * HWSZ;
    float4 bx, by, sg;
    float* bxv = (float*)&bx; float* byv = (float*)&by; float* sgv = (float*)&sg;
#pragma unroll
    for (int i = 0; i < 4; i++) {
        int w = wv[i];
        if (w >= 0) {
            bxv[i] = -__ldg(fb + w);
            byv[i] = -__ldg(fb + HWSZ + w);
            sgv[i] = __ldg(sb + w) ? 1.0f : 0.0f;
        } else {
            bxv[i] = 0.0f; byv[i] = 0.0f; sgv[i] = 0.0f;
        }
    }
    *(float4*)(out + NPIX + b * 2 * HWSZ + p0)        = bx;
    *(float4*)(out + NPIX + b * 2 * HWSZ + HWSZ + p0) = by;
    *(float4*)(out + 3 * NPIX + b * HWSZ + p0)        = sg;
}

extern "C" void kernel_launch(void* const* d_in, const int* in_sizes, int n_in,
                              void* d_out, int out_size) {
    const float* flow  = (const float*)d_in[0];
    const float* depth = (const float*)d_in[1];
    const float* Kmat  = (const float*)d_in[2];
    const float* invK  = (const float*)d_in[3];
    const float* pose  = (const float*)d_in[4];
    const int*   seg   = (const int*)d_in[5];
    float* out = (float*)d_out;

    k_reset<<<1, 32>>>();
    k_reduce1<<<NBLK2, TPB>>>(flow, depth, Kmat, invK, pose);
    k_reduce2<<<NBLK2, TPB>>>(flow, depth, Kmat, invK, pose);
    k_main<<<NBLK2, TPB>>>(flow, depth, Kmat, invK, pose, seg, out);
}

// round 4
// speedup vs baseline: 1.7305x; 1.0301x over previous
#include <cuda_runtime.h>

// ---------------------------------------------------------------------------
// OpticFlowMask: motion mask + flow inversion (winner election + payload gather)
// B=12, H=192, W=640.
// Output layout (float32): [motion_mask (N)][bwd_flow (2N)][seg_ref (N)]
// ---------------------------------------------------------------------------

#define BB    12
#define HH    192
#define WW    640
#define HWSZ  (HH * WW)                 // 122880
#define NPIX  (BB * HWSZ)               // 1474560
#define TPB   256
#define VEC   4
#define PXT   (TPB * VEC)               // 1024 px per block
#define BPB2  (HWSZ / PXT)              // 120 blocks per batch (exact)
#define NBLK2 (BB * BPB2)               // 1440 blocks
#define EPSF  1e-7f
#define THR   0.98f

// reduction slots: 0=fmin 1=fmax 2=smin 3=smax 4=cmin 5=cmax (monotonic-encoded)
__device__ unsigned g_red[6];
__device__ int g_winner[NPIX];
// per-pixel packed payload: (-fx, -fy, seg, check)
__device__ float4 g_payload[NPIX];

__device__ __forceinline__ unsigned fenc(float f) {
    unsigned u = __float_as_uint(f);
    return (u & 0x80000000u) ? ~u : (u | 0x80000000u);
}
__device__ __forceinline__ float fdec(unsigned u) {
    unsigned b = (u & 0x80000000u) ? (u & 0x7fffffffu) : ~u;
    return __uint_as_float(b);
}

template <int SMIN, int SMAX>
__device__ __forceinline__ void block_minmax(float vmin, float vmax) {
#pragma unroll
    for (int o = 16; o; o >>= 1) {
        vmin = fminf(vmin, __shfl_xor_sync(0xffffffffu, vmin, o));
        vmax = fmaxf(vmax, __shfl_xor_sync(0xffffffffu, vmax, o));
    }
    __shared__ float sm1[TPB / 32], sm2[TPB / 32];
    int w = threadIdx.x >> 5, l = threadIdx.x & 31;
    if (l == 0) { sm1[w] = vmin; sm2[w] = vmax; }
    __syncthreads();
    if (w == 0) {
        vmin = (l < TPB / 32) ? sm1[l] : __int_as_float(0x7f800000);   // +inf
        vmax = (l < TPB / 32) ? sm2[l] : __int_as_float(0xff800000);   // -inf
#pragma unroll
        for (int o = 4; o; o >>= 1) {
            vmin = fminf(vmin, __shfl_xor_sync(0xffffffffu, vmin, o));
            vmax = fmaxf(vmax, __shfl_xor_sync(0xffffffffu, vmax, o));
        }
        if (l == 0) {
            atomicMin(&g_red[SMIN], fenc(vmin));
            atomicMax(&g_red[SMAX], fenc(vmax));
        }
    }
}

// Per-block setup of P = (K @ pose)[:3,:] (12 floats) and invK[:3,:3] (9 floats)
__device__ __forceinline__ void setup_mats(const float* Kmat, const float* invK,
                                           const float* pose, int b,
                                           float* sP, float* siK) {
    int t = threadIdx.x;
    if (t < 12) {
        int i = t >> 2, j = t & 3;
        const float* Kb = Kmat + b * 16;
        const float* Pb = pose + b * 16;
        sP[t] = Kb[i * 4 + 0] * Pb[0 * 4 + j] + Kb[i * 4 + 1] * Pb[1 * 4 + j] +
                Kb[i * 4 + 2] * Pb[2 * 4 + j] + Kb[i * 4 + 3] * Pb[3 * 4 + j];
    } else if (t < 21) {
        int r = (t - 12) / 3, c = (t - 12) % 3;
        siK[t - 12] = invK[b * 16 + r * 4 + c];
    }
    __syncthreads();
}

// static flow for 4 consecutive x positions at fixed y
__device__ __forceinline__ void static_flow4(const float* sP, const float* siK,
                                             float x0, float y, const float4& d4,
                                             float* sx, float* sy) {
    const float dv[4] = {d4.x, d4.y, d4.z, d4.w};
#pragma unroll
    for (int i = 0; i < 4; i++) {
        float x = x0 + (float)i;
        float dx = siK[0] * x + (siK[1] * y + siK[2]);
        float dy = siK[3] * x + (siK[4] * y + siK[5]);
        float dz = siK[6] * x + (siK[7] * y + siK[8]);
        float d = dv[i];
        float cx = d * dx, cy = d * dy, cz = d * dz;
        float c0 = sP[0] * cx + sP[1] * cy + sP[2]  * cz + sP[3];
        float c1 = sP[4] * cx + sP[5] * cy + sP[6]  * cz + sP[7];
        float c2 = sP[8] * cx + sP[9] * cy + sP[10] * cz + sP[11];
        float den = c2 + EPSF;
        sx[i] = c0 / den - x;
        sy[i] = c1 / den - y;
    }
}

__global__ void k_reset() {
    int t = threadIdx.x;
    if (t < 6) g_red[t] = (t & 1) ? 0u : 0xffffffffu;
}

// Pass 1: flow min/max + static min/max; reset winner array.
__global__ void __launch_bounds__(TPB) k_reduce1(
        const float* __restrict__ flow, const float* __restrict__ depth,
        const float* __restrict__ Kmat, const float* __restrict__ invK,
        const float* __restrict__ pose) {
    __shared__ float sP[12], siK[9];
    int b = blockIdx.x / BPB2;
    setup_mats(Kmat, invK, pose, b, sP, siK);

    int p0 = (blockIdx.x - b * BPB2) * PXT + threadIdx.x * VEC;
    int y = p0 / WW, x0 = p0 - y * WW;
    const float4 fx4 = *(const float4*)(flow + b * 2 * HWSZ + p0);
    const float4 fy4 = *(const float4*)(flow + b * 2 * HWSZ + HWSZ + p0);
    const float4 d4  = *(const float4*)(depth + b * HWSZ + p0);
    *(int4*)(g_winner + b * HWSZ + p0) = make_int4(-1, -1, -1, -1);

    float sx[4], sy[4];
    static_flow4(sP, siK, (float)x0, (float)y, d4, sx, sy);

    float fmn = fminf(fminf(fminf(fx4.x, fx4.y), fminf(fx4.z, fx4.w)),
                      fminf(fminf(fy4.x, fy4.y), fminf(fy4.z, fy4.w)));
    float fmx = fmaxf(fmaxf(fmaxf(fx4.x, fx4.y), fmaxf(fx4.z, fx4.w)),
                      fmaxf(fmaxf(fy4.x, fy4.y), fmaxf(fy4.z, fy4.w)));
    float smn = fminf(fminf(fminf(sx[0], sx[1]), fminf(sx[2], sx[3])),
                      fminf(fminf(sy[0], sy[1]), fminf(sy[2], sy[3])));
    float smx = fmaxf(fmaxf(fmaxf(sx[0], sx[1]), fmaxf(sx[2], sx[3])),
                      fmaxf(fmaxf(sy[0], sy[1]), fmaxf(sy[2], sy[3])));

    block_minmax<0, 1>(fmn, fmx);
    block_minmax<2, 3>(smn, smx);
}

// Pass 2: check min/max + winner election + packed payload write.
__global__ void __launch_bounds__(TPB) k_reduce2(
        const float* __restrict__ flow, const float* __restrict__ depth,
        const float* __restrict__ Kmat, const float* __restrict__ invK,
        const float* __restrict__ pose, const int* __restrict__ seg) {
    __shared__ float sP[12], siK[9];
    int b = blockIdx.x / BPB2;
    setup_mats(Kmat, invK, pose, b, sP, siK);

    float fmn = fdec(g_red[0]), fmx = fdec(g_red[1]);
    float smn = fdec(g_red[2]), smx = fdec(g_red[3]);
    float finv = 2.0f / (fmx - fmn), sinv = 2.0f / (smx - smn);

    int p0 = (blockIdx.x - b * BPB2) * PXT + threadIdx.x * VEC;
    int idx0 = b * HWSZ + p0;
    int y = p0 / WW, x0 = p0 - y * WW;
    const float4 fx4 = *(const float4*)(flow + b * 2 * HWSZ + p0);
    const float4 fy4 = *(const float4*)(flow + b * 2 * HWSZ + HWSZ + p0);
    const float4 d4  = *(const float4*)(depth + idx0);
    const int4  sg4  = *(const int4*)(seg + idx0);

    float sx[4], sy[4];
    static_flow4(sP, siK, (float)x0, (float)y, d4, sx, sy);

    const float fxv[4] = {fx4.x, fx4.y, fx4.z, fx4.w};
    const float fyv[4] = {fy4.x, fy4.y, fy4.z, fy4.w};
    const int   sgv[4] = {sg4.x, sg4.y, sg4.z, sg4.w};
    float cmn = __int_as_float(0x7f800000), cmx = __int_as_float(0xff800000);
#pragma unroll
    for (int i = 0; i < 4; i++) {
        float ddx = (fxv[i] - fmn) * finv - (sx[i] - smn) * sinv;
        float ddy = (fyv[i] - fmn) * finv - (sy[i] - smn) * sinv;
        float c = sqrtf(ddx * ddx + ddy * ddy);
        cmn = fminf(cmn, c);
        cmx = fmaxf(cmx, c);
        g_payload[idx0 + i] =
            make_float4(-fxv[i], -fyv[i], sgv[i] ? 1.0f : 0.0f, c);
        // winner election: jnp.round = ties-to-even; clip after int cast
        int cxi = min(max((int)rintf((float)(x0 + i) + fxv[i]), 0), WW - 1);
        int cyi = min(max((int)rintf((float)y + fyv[i]), 0), HH - 1);
        atomicMax(&g_winner[b * HWSZ + cyi * WW + cxi], p0 + i);
    }

    block_minmax<4, 5>(cmn, cmx);
}

// Pass 3: motion mask from payload.w + single-load gather per target.
__global__ void __launch_bounds__(TPB) k_main(float* __restrict__ out) {
    float cmn = fdec(g_red[4]), cmx = fdec(g_red[5]);
    float cinv = 1.0f / (cmx - cmn);

    int b = blockIdx.x / BPB2;
    int p0 = (blockIdx.x - b * BPB2) * PXT + threadIdx.x * VEC;
    int idx0 = b * HWSZ + p0;

    const int4 w4 = *(const int4*)(g_winner + idx0);
    const int wv[4] = {w4.x, w4.y, w4.z, w4.w};

    float4 mask, bx, by, sg;
    float* mv = (float*)&mask;
    float* bxv = (float*)&bx; float* byv = (float*)&by; float* sgv = (float*)&sg;
#pragma unroll
    for (int i = 0; i < 4; i++) {
        float c = g_payload[idx0 + i].w;
        mv[i] = ((c - cmn) * cinv < THR) ? 1.0f : 0.0f;
        int w = wv[i];
        if (w >= 0) {
            float4 q = g_payload[b * HWSZ + w];
            bxv[i] = q.x; byv[i] = q.y; sgv[i] = q.z;
        } else {
            bxv[i] = 0.0f; byv[i] = 0.0f; sgv[i] = 0.0f;
        }
    }
    *(float4*)(out + idx0)                            = mask;
    *(float4*)(out + NPIX + b * 2 * HWSZ + p0)        = bx;
    *(float4*)(out + NPIX + b * 2 * HWSZ + HWSZ + p0) = by;
    *(float4*)(out + 3 * NPIX + idx0)                 = sg;
}

extern "C" void kernel_launch(void* const* d_in, const int* in_sizes, int n_in,
                              void* d_out, int out_size) {
    const float* flow  = (const float*)d_in[0];
    const float* depth = (const float*)d_in[1];
    const float* Kmat  = (const float*)d_in[2];
    const float* invK  = (const float*)d_in[3];
    const float* pose  = (const float*)d_in[4];
    const int*   seg   = (const int*)d_in[5];
    float* out = (float*)d_out;

    k_reset<<<1, 32>>>();
    k_reduce1<<<NBLK2, TPB>>>(flow, depth, Kmat, invK, pose);
    k_reduce2<<<NBLK2, TPB>>>(flow, depth, Kmat, invK, pose, seg);
    k_main<<<NBLK2, TPB>>>(out);
}